// round 1
// baseline (speedup 1.0000x reference)
#include <cuda_runtime.h>

// ---------------- problem constants ----------------
#define DD     256          // hidden width
#define LG     6            // levels / layers
#define TSZ    524288       // hash table size per level (2^19)
#define TMASK  0x7FFFFu
#define MPTS   64           // points per CTA
#define NTHR   256          // threads per CTA
#define KB     32           // K-chunk for weight staging
#define NCH    8            // 256 / KB
#define MPAD   68           // padded row length for x^T tile (multiple of 4)

#define W0S    5.0f         // sin_w0 = L-1
#define W0H    10.0f        // sin_w0_high = 2*(L-1)

#define SX_FLOATS (DD * MPAD)           // 17408
#define SW_FLOATS (2 * KB * DD)         // 16384
#define SG_FLOATS (MPTS * LG * 2)       // 768
#define SP_FLOATS (MPTS * 3)            // 192
#define SMEM_BYTES ((SX_FLOATS + SW_FLOATS + SG_FLOATS + SP_FLOATS) * 4)

// ---------------- packed fp32x2 helpers (Blackwell double-rate fp32) ----------------
static __device__ __forceinline__ unsigned long long pk2(float x, float y) {
    unsigned long long r;
    asm("mov.b64 %0, {%1, %2};" : "=l"(r) : "f"(x), "f"(y));
    return r;
}
static __device__ __forceinline__ void upk2(unsigned long long v, float &x, float &y) {
    asm("mov.b64 {%0, %1}, %2;" : "=f"(x), "=f"(y) : "l"(v));
}
static __device__ __forceinline__ void ffma2(unsigned long long &d,
                                             unsigned long long a,
                                             unsigned long long b) {
    asm("fma.rn.f32x2 %0, %1, %2, %0;" : "+l"(d) : "l"(a), "l"(b));
}

__global__ void __launch_bounds__(NTHR, 1)
ffb_kernel(const float* __restrict__ gpos,   // [N,3]
           const float* __restrict__ gtable, // [L,T,2]
           const float* __restrict__ gA,     // [L,2,256]
           const float* __restrict__ gW0,    // [3,256]
           const float* __restrict__ gb0,    // [256]
           const float* __restrict__ gWs,    // [L,256,256]
           const float* __restrict__ gbs,    // [L,256]
           const float* __restrict__ gWh,    // [L,256,256]
           const float* __restrict__ gbh,    // [L,256]
           float* __restrict__ gout)         // [N,256]
{
    extern __shared__ float smem[];
    float (*sxT)[MPAD]  = (float (*)[MPAD])smem;                            // x^T [k][m]
    float (*sW)[KB][DD] = (float (*)[KB][DD])(smem + SX_FLOATS);            // weight chunks, double buffer
    float (*sg)[LG][2]  = (float (*)[LG][2])(smem + SX_FLOATS + SW_FLOATS); // grid features
    float (*sp)[3]      = (float (*)[3])(smem + SX_FLOATS + SW_FLOATS + SG_FLOATS);

    const int tid = threadIdx.x;
    const int ct  = tid & 31;        // column tile (d)
    const int rt  = tid >> 5;        // row tile (m) == warp id
    const int d0  = ct * 8;
    const int m0  = rt * 8;
    const int base = blockIdx.x * MPTS;

    // ---- load positions ----
    for (int i = tid; i < MPTS * 3; i += NTHR)
        sp[i / 3][i % 3] = gpos[(size_t)base * 3 + i];
    __syncthreads();

    // ---- hash-grid encode: 64 points x 6 levels ----
    for (int t = tid; t < MPTS * LG; t += NTHR) {
        const int m = t / LG;
        const int l = t % LG;
        const float scale = (float)(16 << l);
        const float px = (sp[m][0] + 1.0f) * 0.5f * scale;
        const float py = (sp[m][1] + 1.0f) * 0.5f * scale;
        const float pz = (sp[m][2] + 1.0f) * 0.5f * scale;
        const float fx = floorf(px), fy = floorf(py), fz = floorf(pz);
        const float rx = px - fx, ry = py - fy, rz = pz - fz;
        const unsigned int ix = (unsigned int)(int)fx;
        const unsigned int iy = (unsigned int)(int)fy;
        const unsigned int iz = (unsigned int)(int)fz;
        const float2* tb = (const float2*)gtable + (size_t)l * TSZ;
        float g0 = 0.0f, g1 = 0.0f;
        #pragma unroll
        for (int c = 0; c < 8; ++c) {
            const unsigned int bi = (c >> 2) & 1u;
            const unsigned int bj = (c >> 1) & 1u;
            const unsigned int bk = c & 1u;
            const unsigned int h = ((ix + bi)
                                  ^ ((iy + bj) * 2654435761u)
                                  ^ ((iz + bk) * 805459861u)) & TMASK;
            const float2 f = __ldg(&tb[h]);
            const float w = (bi ? rx : 1.0f - rx)
                          * (bj ? ry : 1.0f - ry)
                          * (bk ? rz : 1.0f - rz);
            g0 = fmaf(w, f.x, g0);
            g1 = fmaf(w, f.y, g1);
        }
        sg[m][l][0] = g0;
        sg[m][l][1] = g1;
    }
    __syncthreads();

    // ---- layer 0: x = sin(5*(pos @ W0 + b0)), write x^T to smem ----
    {
        float w0r[3][8];
        #pragma unroll
        for (int k = 0; k < 3; ++k) {
            const float4 a = __ldg((const float4*)(gW0 + k * DD + d0));
            const float4 b = __ldg((const float4*)(gW0 + k * DD + d0 + 4));
            w0r[k][0] = a.x; w0r[k][1] = a.y; w0r[k][2] = a.z; w0r[k][3] = a.w;
            w0r[k][4] = b.x; w0r[k][5] = b.y; w0r[k][6] = b.z; w0r[k][7] = b.w;
        }
        const float4 ba = __ldg((const float4*)(gb0 + d0));
        const float4 bb4 = __ldg((const float4*)(gb0 + d0 + 4));
        const float bb[8] = {ba.x, ba.y, ba.z, ba.w, bb4.x, bb4.y, bb4.z, bb4.w};
        #pragma unroll
        for (int i = 0; i < 8; ++i) {
            const float px = sp[m0 + i][0];
            const float py = sp[m0 + i][1];
            const float pz = sp[m0 + i][2];
            #pragma unroll
            for (int j = 0; j < 8; ++j) {
                const float v = fmaf(px, w0r[0][j], fmaf(py, w0r[1][j], fmaf(pz, w0r[2][j], bb[j])));
                sxT[d0 + j][m0 + i] = __sinf(W0S * v);
            }
        }
    }
    // (visibility of sxT handled by the first __syncthreads inside the GEMM)

    unsigned long long acc[8][4];  // z tile, pairs over d
    float oacc[8][8];              // output accumulator
    #pragma unroll
    for (int i = 0; i < 8; ++i)
        #pragma unroll
        for (int j = 0; j < 8; ++j) oacc[i][j] = 0.0f;

    // GEMM: acc[m0..][d0..] = sum_k sxT[k][m] * Wg[k][d]
    auto gemm = [&](const float* __restrict__ Wg) {
        #pragma unroll
        for (int i = 0; i < 8; ++i)
            #pragma unroll
            for (int jp = 0; jp < 4; ++jp) acc[i][jp] = 0ULL;

        float4 st[8];
        {
            const float4* src = (const float4*)Wg;
            #pragma unroll
            for (int q = 0; q < 8; ++q) st[q] = __ldg(&src[tid + q * NTHR]);
        }
        int buf = 0;
        #pragma unroll 1
        for (int c = 0; c < NCH; ++c) {
            __syncthreads();    // previous users of sW[buf] / sxT writers done
            {
                float4* dst = (float4*)&sW[buf][0][0];
                #pragma unroll
                for (int q = 0; q < 8; ++q) dst[tid + q * NTHR] = st[q];
            }
            __syncthreads();
            if (c + 1 < NCH) {
                const float4* src = (const float4*)(Wg + (size_t)(c + 1) * KB * DD);
                #pragma unroll
                for (int q = 0; q < 8; ++q) st[q] = __ldg(&src[tid + q * NTHR]);
            }
            const int k0 = c * KB;
            #pragma unroll 8
            for (int kk = 0; kk < KB; ++kk) {
                const float4 xa = *(const float4*)&sxT[k0 + kk][m0];
                const float4 xb = *(const float4*)&sxT[k0 + kk][m0 + 4];
                const ulonglong2* wr = (const ulonglong2*)&sW[buf][kk][d0];
                const ulonglong2 wA = wr[0];
                const ulonglong2 wB = wr[1];
                const float xv[8] = {xa.x, xa.y, xa.z, xa.w, xb.x, xb.y, xb.z, xb.w};
                #pragma unroll
                for (int i = 0; i < 8; ++i) {
                    const unsigned long long ax = pk2(xv[i], xv[i]);
                    ffma2(acc[i][0], ax, wA.x);
                    ffma2(acc[i][1], ax, wA.y);
                    ffma2(acc[i][2], ax, wB.x);
                    ffma2(acc[i][3], ax, wB.y);
                }
            }
            buf ^= 1;
        }
    };

    #pragma unroll 1
    for (int layer = 0; layer < LG; ++layer) {
        // ---- z = x @ Ws[layer] ----
        gemm(gWs + (size_t)layer * DD * DD);

        // ---- epilogue 1: x = sin(5*(z+bs)) + sin(2*pi*sigma*(g @ A)) ----
        __syncthreads();   // all warps finished reading sxT before overwrite
        {
            const float* A0p = gA + ((size_t)layer * 2 + 0) * DD + d0;
            const float* A1p = gA + ((size_t)layer * 2 + 1) * DD + d0;
            const float4 a0a = __ldg((const float4*)A0p);
            const float4 a0b = __ldg((const float4*)(A0p + 4));
            const float4 a1a = __ldg((const float4*)A1p);
            const float4 a1b = __ldg((const float4*)(A1p + 4));
            const float A0[8] = {a0a.x, a0a.y, a0a.z, a0a.w, a0b.x, a0b.y, a0b.z, a0b.w};
            const float A1[8] = {a1a.x, a1a.y, a1a.z, a1a.w, a1b.x, a1b.y, a1b.z, a1b.w};
            const float4 bsa = __ldg((const float4*)(gbs + layer * DD + d0));
            const float4 bsb = __ldg((const float4*)(gbs + layer * DD + d0 + 4));
            const float bb[8] = {bsa.x, bsa.y, bsa.z, bsa.w, bsb.x, bsb.y, bsb.z, bsb.w};
            const float sig2pi = 6.283185307179586f * (5.0f * (float)(1 << layer));
            #pragma unroll
            for (int i = 0; i < 8; ++i) {
                const float g0 = sg[m0 + i][layer][0];
                const float g1 = sg[m0 + i][layer][1];
                #pragma unroll
                for (int jp = 0; jp < 4; ++jp) {
                    float z0, z1;
                    upk2(acc[i][jp], z0, z1);
                    const float ga = sig2pi * fmaf(g0, A0[2 * jp],     g1 * A1[2 * jp]);
                    const float gb = sig2pi * fmaf(g0, A0[2 * jp + 1], g1 * A1[2 * jp + 1]);
                    sxT[d0 + 2 * jp][m0 + i]     = __sinf(W0S * (z0 + bb[2 * jp]))     + __sinf(ga);
                    sxT[d0 + 2 * jp + 1][m0 + i] = __sinf(W0S * (z1 + bb[2 * jp + 1])) + __sinf(gb);
                }
            }
        }
        // sxT write -> read ordering handled by first sync inside next gemm

        // ---- z2 = x @ Wh[layer] ----
        gemm(gWh + (size_t)layer * DD * DD);

        // ---- epilogue 2: out += sin(10*(z2+bh)) ----
        {
            const float4 bha = __ldg((const float4*)(gbh + layer * DD + d0));
            const float4 bhb = __ldg((const float4*)(gbh + layer * DD + d0 + 4));
            const float bb[8] = {bha.x, bha.y, bha.z, bha.w, bhb.x, bhb.y, bhb.z, bhb.w};
            #pragma unroll
            for (int i = 0; i < 8; ++i) {
                #pragma unroll
                for (int jp = 0; jp < 4; ++jp) {
                    float z0, z1;
                    upk2(acc[i][jp], z0, z1);
                    oacc[i][2 * jp]     += __sinf(W0H * (z0 + bb[2 * jp]));
                    oacc[i][2 * jp + 1] += __sinf(W0H * (z1 + bb[2 * jp + 1]));
                }
            }
        }
    }

    // ---- write output ----
    #pragma unroll
    for (int i = 0; i < 8; ++i) {
        float* orow = gout + (size_t)(base + m0 + i) * DD + d0;
        *(float4*)orow       = make_float4(oacc[i][0], oacc[i][1], oacc[i][2], oacc[i][3]);
        *((float4*)orow + 1) = make_float4(oacc[i][4], oacc[i][5], oacc[i][6], oacc[i][7]);
    }
}

extern "C" void kernel_launch(void* const* d_in, const int* in_sizes, int n_in,
                              void* d_out, int out_size) {
    const float* gpos   = (const float*)d_in[0];
    const float* gtable = (const float*)d_in[1];
    const float* gA     = (const float*)d_in[2];
    const float* gW0    = (const float*)d_in[3];
    const float* gb0    = (const float*)d_in[4];
    const float* gWs    = (const float*)d_in[5];
    const float* gbs    = (const float*)d_in[6];
    const float* gWh    = (const float*)d_in[7];
    const float* gbh    = (const float*)d_in[8];
    float* gout = (float*)d_out;

    const int n = in_sizes[0] / 3;
    cudaFuncSetAttribute(ffb_kernel, cudaFuncAttributeMaxDynamicSharedMemorySize, SMEM_BYTES);
    ffb_kernel<<<n / MPTS, NTHR, SMEM_BYTES>>>(gpos, gtable, gA, gW0, gb0,
                                               gWs, gbs, gWh, gbh, gout);
}

// round 2
// speedup vs baseline: 1.1977x; 1.1977x over previous
#include <cuda_runtime.h>
#include <cstdint>

// ---------------- problem constants ----------------
#define DD     256          // hidden width
#define LG     6            // levels / layers
#define TSZ    524288       // hash table size per level (2^19)
#define TMASK  0x7FFFFu
#define MPTS   64           // points per CTA
#define NTHR   256          // threads per CTA
#define KB     16           // K-chunk rows for weight staging
#define NCH    16           // 256 / KB

#define W0S    5.0f         // sin_w0 = L-1
#define W0H    10.0f        // sin_w0_high = 2*(L-1)

#define SX_FLOATS (DD * 64)             // 16384  x^T tile, swizzled, [d][64]
#define SW_FLOATS (2 * KB * DD)         // 8192   weight chunks, double buffer
#define SG_FLOATS (MPTS * LG * 2)       // 768
#define SP_FLOATS (MPTS * 3)            // 192
#define SMEM_BYTES ((SX_FLOATS + SW_FLOATS + SG_FLOATS + SP_FLOATS) * 4)

// ---------------- packed fp32x2 helpers ----------------
static __device__ __forceinline__ unsigned long long pk2(float x, float y) {
    unsigned long long r;
    asm("mov.b64 %0, {%1, %2};" : "=l"(r) : "f"(x), "f"(y));
    return r;
}
static __device__ __forceinline__ void upk2(unsigned long long v, float &x, float &y) {
    asm("mov.b64 {%0, %1}, %2;" : "=f"(x), "=f"(y) : "l"(v));
}
static __device__ __forceinline__ void ffma2(unsigned long long &d,
                                             unsigned long long a,
                                             unsigned long long b) {
    asm("fma.rn.f32x2 %0, %1, %2, %0;" : "+l"(d) : "l"(a), "l"(b));
}

// ---------------- cp.async helpers ----------------
static __device__ __forceinline__ void cp16(uint32_t saddr, const void* gaddr) {
    asm volatile("cp.async.cg.shared.global [%0], [%1], 16;" :: "r"(saddr), "l"(gaddr));
}
static __device__ __forceinline__ void cp_commit() {
    asm volatile("cp.async.commit_group;" ::: "memory");
}
static __device__ __forceinline__ void cp_wait0() {
    asm volatile("cp.async.wait_group 0;" ::: "memory");
}

__global__ void __launch_bounds__(NTHR, 2)
ffb_kernel(const float* __restrict__ gpos,   // [N,3]
           const float* __restrict__ gtable, // [L,T,2]
           const float* __restrict__ gA,     // [L,2,256]
           const float* __restrict__ gW0,    // [3,256]
           const float* __restrict__ gb0,    // [256]
           const float* __restrict__ gWs,    // [L,256,256]
           const float* __restrict__ gbs,    // [L,256]
           const float* __restrict__ gWh,    // [L,256,256]
           const float* __restrict__ gbh,    // [L,256]
           float* __restrict__ gout)         // [N,256]
{
    extern __shared__ float smem[];
    float* sx = smem;                                   // x^T, swizzled [d][64]
    float* sW = smem + SX_FLOATS;                       // [2][KB][256]
    float (*sg)[LG][2] = (float (*)[LG][2])(smem + SX_FLOATS + SW_FLOATS);
    float (*sp)[3]     = (float (*)[3])(smem + SX_FLOATS + SW_FLOATS + SG_FLOATS);

    const int tid = threadIdx.x;
    const int ct  = tid & 31;        // column tile (d): owns ct*4..+3 and 128+ct*4..+3
    const int rt  = tid >> 5;        // warp id -> m tile
    const int m0  = rt * 8;
    const int mg0 = m0 >> 2;         // logical m-group (even)
    const int xkey = ct & 15;        // swizzle key for this thread's d rows
    const int base = blockIdx.x * MPTS;
    const uint32_t sW_base = (uint32_t)__cvta_generic_to_shared(sW);

    // ---- load positions ----
    for (int i = tid; i < MPTS * 3; i += NTHR)
        sp[i / 3][i % 3] = gpos[(size_t)base * 3 + i];
    __syncthreads();

    // ---- hash-grid encode: 64 points x 6 levels ----
    for (int t = tid; t < MPTS * LG; t += NTHR) {
        const int m = t / LG;
        const int l = t % LG;
        const float scale = (float)(16 << l);
        const float px = (sp[m][0] + 1.0f) * 0.5f * scale;
        const float py = (sp[m][1] + 1.0f) * 0.5f * scale;
        const float pz = (sp[m][2] + 1.0f) * 0.5f * scale;
        const float fx = floorf(px), fy = floorf(py), fz = floorf(pz);
        const float rx = px - fx, ry = py - fy, rz = pz - fz;
        const unsigned int ix = (unsigned int)(int)fx;
        const unsigned int iy = (unsigned int)(int)fy;
        const unsigned int iz = (unsigned int)(int)fz;
        const float2* tb = (const float2*)gtable + (size_t)l * TSZ;
        float g0 = 0.0f, g1 = 0.0f;
        #pragma unroll
        for (int c = 0; c < 8; ++c) {
            const unsigned int bi = (c >> 2) & 1u;
            const unsigned int bj = (c >> 1) & 1u;
            const unsigned int bk = c & 1u;
            const unsigned int h = ((ix + bi)
                                  ^ ((iy + bj) * 2654435761u)
                                  ^ ((iz + bk) * 805459861u)) & TMASK;
            const float2 f = __ldg(&tb[h]);
            const float w = (bi ? rx : 1.0f - rx)
                          * (bj ? ry : 1.0f - ry)
                          * (bk ? rz : 1.0f - rz);
            g0 = fmaf(w, f.x, g0);
            g1 = fmaf(w, f.y, g1);
        }
        sg[m][l][0] = g0;
        sg[m][l][1] = g1;
    }
    __syncthreads();

    // ---- layer 0: x = sin(5*(pos @ W0 + b0)) -> swizzled x^T in smem ----
    {
        float pxr[8], pyr[8], pzr[8];
        #pragma unroll
        for (int i = 0; i < 8; ++i) {
            pxr[i] = sp[m0 + i][0];
            pyr[i] = sp[m0 + i][1];
            pzr[i] = sp[m0 + i][2];
        }
        float w0A[3][4], w0B[3][4];
        #pragma unroll
        for (int k = 0; k < 3; ++k) {
            const float4 a = __ldg((const float4*)(gW0 + k * DD + ct * 4));
            const float4 b = __ldg((const float4*)(gW0 + k * DD + 128 + ct * 4));
            w0A[k][0] = a.x; w0A[k][1] = a.y; w0A[k][2] = a.z; w0A[k][3] = a.w;
            w0B[k][0] = b.x; w0B[k][1] = b.y; w0B[k][2] = b.z; w0B[k][3] = b.w;
        }
        const float4 b0a = __ldg((const float4*)(gb0 + ct * 4));
        const float4 b0b = __ldg((const float4*)(gb0 + 128 + ct * 4));
        const float bA[4] = {b0a.x, b0a.y, b0a.z, b0a.w};
        const float bB[4] = {b0b.x, b0b.y, b0b.z, b0b.w};
        #pragma unroll
        for (int j = 0; j < 4; ++j) {
            float vA[8], vB[8];
            #pragma unroll
            for (int i = 0; i < 8; ++i) {
                vA[i] = __sinf(W0S * fmaf(pxr[i], w0A[0][j],
                               fmaf(pyr[i], w0A[1][j], fmaf(pzr[i], w0A[2][j], bA[j]))));
                vB[i] = __sinf(W0S * fmaf(pxr[i], w0B[0][j],
                               fmaf(pyr[i], w0B[1][j], fmaf(pzr[i], w0B[2][j], bB[j]))));
            }
            const int dA = ct * 4 + j;
            const int wA0 = dA * 64 + ((mg0 ^ xkey) << 2);
            *(float4*)(sx + wA0)            = make_float4(vA[0], vA[1], vA[2], vA[3]);
            *(float4*)(sx + (wA0 ^ 4))      = make_float4(vA[4], vA[5], vA[6], vA[7]);
            const int wB0 = wA0 + 128 * 64;
            *(float4*)(sx + wB0)            = make_float4(vB[0], vB[1], vB[2], vB[3]);
            *(float4*)(sx + (wB0 ^ 4))      = make_float4(vB[4], vB[5], vB[6], vB[7]);
        }
    }
    // sxT visibility handled by the barrier inside gemm's first iteration

    unsigned long long acc[8][4];  // [m][pair]: pairs (A0,A1),(A2,A3),(B0,B1),(B2,B3)

    // GEMM: acc = x @ Wg  (x read from swizzled sx, Wg streamed via cp.async)
    auto gemm = [&](const float* __restrict__ Wg) {
        #pragma unroll
        for (int i = 0; i < 8; ++i)
            #pragma unroll
            for (int jp = 0; jp < 4; ++jp) acc[i][jp] = 0ULL;

        // prologue: chunk 0 -> buf 0
        {
            const uint32_t dst = sW_base + tid * 16;
            const char* src = (const char*)Wg + tid * 16;
            #pragma unroll
            for (int q = 0; q < 4; ++q) cp16(dst + q * 4096, src + q * 4096);
            cp_commit();
        }
        #pragma unroll 1
        for (int c = 0; c < NCH; ++c) {
            cp_wait0();
            __syncthreads();
            if (c + 1 < NCH) {
                const uint32_t dst = sW_base + ((c + 1) & 1) * (KB * DD * 4) + tid * 16;
                const char* src = (const char*)Wg + (size_t)(c + 1) * KB * DD * 4 + tid * 16;
                #pragma unroll
                for (int q = 0; q < 4; ++q) cp16(dst + q * 4096, src + q * 4096);
                cp_commit();
            }
            const float* swb = sW + (c & 1) * (KB * DD);
            const int k0 = c * KB;
            #pragma unroll
            for (int kk = 0; kk < KB; ++kk) {
                const int k = k0 + kk;
                const int gw = ((mg0 ^ ((k >> 2) & 15)) << 2);
                const float* xrow = sx + k * 64;
                const float4 xa = *(const float4*)(xrow + gw);
                const float4 xb = *(const float4*)(xrow + (gw ^ 4));
                const ulonglong2 wA = *(const ulonglong2*)(swb + kk * DD + (ct << 2));
                const ulonglong2 wB = *(const ulonglong2*)(swb + kk * DD + 128 + (ct << 2));
                const float xv[8] = {xa.x, xa.y, xa.z, xa.w, xb.x, xb.y, xb.z, xb.w};
                #pragma unroll
                for (int i = 0; i < 8; ++i) {
                    const unsigned long long ax = pk2(xv[i], xv[i]);
                    ffma2(acc[i][0], ax, wA.x);
                    ffma2(acc[i][1], ax, wA.y);
                    ffma2(acc[i][2], ax, wB.x);
                    ffma2(acc[i][3], ax, wB.y);
                }
            }
        }
    };

    #pragma unroll 1
    for (int layer = 0; layer < LG; ++layer) {
        // ---- z = x @ Ws[layer] ----
        gemm(gWs + (size_t)layer * DD * DD);

        // ---- epilogue 1: x = sin(5*(z+bs)) + sin(2*pi*sigma*(g @ A)) ----
        __syncthreads();   // all warps done reading sx before overwrite
        {
            const float4 a0A = __ldg((const float4*)(gA + ((size_t)layer * 2 + 0) * DD + ct * 4));
            const float4 a0B = __ldg((const float4*)(gA + ((size_t)layer * 2 + 0) * DD + 128 + ct * 4));
            const float4 a1A = __ldg((const float4*)(gA + ((size_t)layer * 2 + 1) * DD + ct * 4));
            const float4 a1B = __ldg((const float4*)(gA + ((size_t)layer * 2 + 1) * DD + 128 + ct * 4));
            const float4 bsA4 = __ldg((const float4*)(gbs + layer * DD + ct * 4));
            const float4 bsB4 = __ldg((const float4*)(gbs + layer * DD + 128 + ct * 4));
            const float A0A[4] = {a0A.x, a0A.y, a0A.z, a0A.w};
            const float A0B[4] = {a0B.x, a0B.y, a0B.z, a0B.w};
            const float A1A[4] = {a1A.x, a1A.y, a1A.z, a1A.w};
            const float A1B[4] = {a1B.x, a1B.y, a1B.z, a1B.w};
            const float bsA[4] = {bsA4.x, bsA4.y, bsA4.z, bsA4.w};
            const float bsB[4] = {bsB4.x, bsB4.y, bsB4.z, bsB4.w};
            float g0r[8], g1r[8];
            #pragma unroll
            for (int i = 0; i < 8; ++i) {
                g0r[i] = sg[m0 + i][layer][0];
                g1r[i] = sg[m0 + i][layer][1];
            }
            const float sig2pi = 6.283185307179586f * (5.0f * (float)(1 << layer));
            #pragma unroll
            for (int jp = 0; jp < 2; ++jp) {
                float vA0[8], vA1[8], vB0[8], vB1[8];
                #pragma unroll
                for (int i = 0; i < 8; ++i) {
                    float zA0, zA1, zB0, zB1;
                    upk2(acc[i][jp], zA0, zA1);
                    upk2(acc[i][2 + jp], zB0, zB1);
                    const float gA0 = sig2pi * fmaf(g0r[i], A0A[2*jp],   g1r[i] * A1A[2*jp]);
                    const float gA1 = sig2pi * fmaf(g0r[i], A0A[2*jp+1], g1r[i] * A1A[2*jp+1]);
                    const float gB0 = sig2pi * fmaf(g0r[i], A0B[2*jp],   g1r[i] * A1B[2*jp]);
                    const float gB1 = sig2pi * fmaf(g0r[i], A0B[2*jp+1], g1r[i] * A1B[2*jp+1]);
                    vA0[i] = __sinf(W0S * (zA0 + bsA[2*jp]))   + __sinf(gA0);
                    vA1[i] = __sinf(W0S * (zA1 + bsA[2*jp+1])) + __sinf(gA1);
                    vB0[i] = __sinf(W0S * (zB0 + bsB[2*jp]))   + __sinf(gB0);
                    vB1[i] = __sinf(W0S * (zB1 + bsB[2*jp+1])) + __sinf(gB1);
                }
                #pragma unroll
                for (int s = 0; s < 2; ++s) {
                    const float* vA = s ? vA1 : vA0;
                    const float* vB = s ? vB1 : vB0;
                    const int dA = ct * 4 + 2 * jp + s;
                    const int wA0 = dA * 64 + ((mg0 ^ xkey) << 2);
                    *(float4*)(sx + wA0)       = make_float4(vA[0], vA[1], vA[2], vA[3]);
                    *(float4*)(sx + (wA0 ^ 4)) = make_float4(vA[4], vA[5], vA[6], vA[7]);
                    const int wB0 = wA0 + 128 * 64;
                    *(float4*)(sx + wB0)       = make_float4(vB[0], vB[1], vB[2], vB[3]);
                    *(float4*)(sx + (wB0 ^ 4)) = make_float4(vB[4], vB[5], vB[6], vB[7]);
                }
            }
        }
        // write -> read ordering handled by barrier in next gemm iter 0

        // ---- z2 = x @ Wh[layer] ----
        gemm(gWh + (size_t)layer * DD * DD);

        // ---- epilogue 2: gout (+)= sin(10*(z2+bh)) ----
        {
            const float4 bhA4 = __ldg((const float4*)(gbh + layer * DD + ct * 4));
            const float4 bhB4 = __ldg((const float4*)(gbh + layer * DD + 128 + ct * 4));
            const float bhA[4] = {bhA4.x, bhA4.y, bhA4.z, bhA4.w};
            const float bhB[4] = {bhB4.x, bhB4.y, bhB4.z, bhB4.w};
            #pragma unroll
            for (int i = 0; i < 8; ++i) {
                float sA[4], sB[4];
                #pragma unroll
                for (int jp = 0; jp < 2; ++jp) {
                    float zA0, zA1, zB0, zB1;
                    upk2(acc[i][jp], zA0, zA1);
                    upk2(acc[i][2 + jp], zB0, zB1);
                    sA[2*jp]   = __sinf(W0H * (zA0 + bhA[2*jp]));
                    sA[2*jp+1] = __sinf(W0H * (zA1 + bhA[2*jp+1]));
                    sB[2*jp]   = __sinf(W0H * (zB0 + bhB[2*jp]));
                    sB[2*jp+1] = __sinf(W0H * (zB1 + bhB[2*jp+1]));
                }
                float* orowA = gout + (size_t)(base + m0 + i) * DD + ct * 4;
                float* orowB = orowA + 128;
                if (layer == 0) {
                    *(float4*)orowA = make_float4(sA[0], sA[1], sA[2], sA[3]);
                    *(float4*)orowB = make_float4(sB[0], sB[1], sB[2], sB[3]);
                } else {
                    float4 oA = *(const float4*)orowA;
                    float4 oB = *(const float4*)orowB;
                    oA.x += sA[0]; oA.y += sA[1]; oA.z += sA[2]; oA.w += sA[3];
                    oB.x += sB[0]; oB.y += sB[1]; oB.z += sB[2]; oB.w += sB[3];
                    *(float4*)orowA = oA;
                    *(float4*)orowB = oB;
                }
            }
        }
    }
}

extern "C" void kernel_launch(void* const* d_in, const int* in_sizes, int n_in,
                              void* d_out, int out_size) {
    const float* gpos   = (const float*)d_in[0];
    const float* gtable = (const float*)d_in[1];
    const float* gA     = (const float*)d_in[2];
    const float* gW0    = (const float*)d_in[3];
    const float* gb0    = (const float*)d_in[4];
    const float* gWs    = (const float*)d_in[5];
    const float* gbs    = (const float*)d_in[6];
    const float* gWh    = (const float*)d_in[7];
    const float* gbh    = (const float*)d_in[8];
    float* gout = (float*)d_out;

    const int n = in_sizes[0] / 3;
    cudaFuncSetAttribute(ffb_kernel, cudaFuncAttributeMaxDynamicSharedMemorySize, SMEM_BYTES);
    ffb_kernel<<<n / MPTS, NTHR, SMEM_BYTES>>>(gpos, gtable, gA, gW0, gb0,
                                               gWs, gbs, gWh, gbh, gout);
}

// round 3
// speedup vs baseline: 1.2657x; 1.0568x over previous
#include <cuda_runtime.h>
#include <cstdint>

// ---------------- problem constants ----------------
#define DD     256          // hidden width
#define LG     6            // levels / layers
#define TSZ    524288       // hash table size per level (2^19)
#define TMASK  0x7FFFFu
#define MPTS   64           // points per CTA
#define NTHR   256          // threads per CTA
#define KB     16           // K-chunk rows for weight staging
#define NCH    16           // 256 / KB

#define W0S    5.0f         // sin_w0 = L-1
#define W0H    10.0f        // sin_w0_high = 2*(L-1)

#define SX_FLOATS (DD * 64)             // 16384  x^T tile, swizzled, [d][64]
#define SW_FLOATS (2 * KB * DD)         // 8192   weight chunks, double buffer
#define SG_FLOATS (MPTS * LG * 2)       // 768
#define SP_FLOATS (MPTS * 3)            // 192
#define SMEM_BYTES ((SX_FLOATS + SW_FLOATS + SG_FLOATS + SP_FLOATS) * 4)

// ---------------- packed fp32x2 helpers ----------------
static __device__ __forceinline__ unsigned long long pk2(float x, float y) {
    unsigned long long r;
    asm("mov.b64 %0, {%1, %2};" : "=l"(r) : "f"(x), "f"(y));
    return r;
}
static __device__ __forceinline__ void upk2(unsigned long long v, float &x, float &y) {
    asm("mov.b64 {%0, %1}, %2;" : "=f"(x), "=f"(y) : "l"(v));
}
static __device__ __forceinline__ void ffma2(unsigned long long &d,
                                             unsigned long long a,
                                             unsigned long long b) {
    asm("fma.rn.f32x2 %0, %1, %2, %0;" : "+l"(d) : "l"(a), "l"(b));
}

// ---------------- cp.async helpers ----------------
static __device__ __forceinline__ void cp16(uint32_t saddr, const void* gaddr) {
    asm volatile("cp.async.cg.shared.global [%0], [%1], 16;" :: "r"(saddr), "l"(gaddr));
}
static __device__ __forceinline__ void cp_commit() {
    asm volatile("cp.async.commit_group;" ::: "memory");
}
static __device__ __forceinline__ void cp_wait0() {
    asm volatile("cp.async.wait_group 0;" ::: "memory");
}

__global__ void __launch_bounds__(NTHR, 2)
ffb_kernel(const float* __restrict__ gpos,   // [N,3]
           const float* __restrict__ gtable, // [L,T,2]
           const float* __restrict__ gA,     // [L,2,256]
           const float* __restrict__ gW0,    // [3,256]
           const float* __restrict__ gb0,    // [256]
           const float* __restrict__ gWs,    // [L,256,256]
           const float* __restrict__ gbs,    // [L,256]
           const float* __restrict__ gWh,    // [L,256,256]
           const float* __restrict__ gbh,    // [L,256]
           float* __restrict__ gout)         // [N,256]
{
    extern __shared__ float smem[];
    float* sx = smem;                                   // x^T, swizzled [d][64]
    float* sW = smem + SX_FLOATS;                       // [2][KB][256]
    float (*sg)[LG][2] = (float (*)[LG][2])(smem + SX_FLOATS + SW_FLOATS);
    float (*sp)[3]     = (float (*)[3])(smem + SX_FLOATS + SW_FLOATS + SG_FLOATS);

    const int tid = threadIdx.x;
    const int ct  = tid & 31;        // column tile (d): owns ct*4..+3 and 128+ct*4..+3
    const int rt  = tid >> 5;        // warp id -> m tile
    const int m0  = rt * 8;
    const int mg0 = m0 >> 2;         // logical m-group (even)
    const int xkey = ct & 15;        // swizzle key for this thread's d rows
    const int base = blockIdx.x * MPTS;
    const uint32_t sW_base = (uint32_t)__cvta_generic_to_shared(sW);

    // ---- load positions ----
    for (int i = tid; i < MPTS * 3; i += NTHR)
        sp[i / 3][i % 3] = gpos[(size_t)base * 3 + i];
    __syncthreads();

    // ---- hash-grid encode: 64 points x 6 levels ----
    for (int t = tid; t < MPTS * LG; t += NTHR) {
        const int m = t / LG;
        const int l = t % LG;
        const float scale = (float)(16 << l);
        const float px = (sp[m][0] + 1.0f) * 0.5f * scale;
        const float py = (sp[m][1] + 1.0f) * 0.5f * scale;
        const float pz = (sp[m][2] + 1.0f) * 0.5f * scale;
        const float fx = floorf(px), fy = floorf(py), fz = floorf(pz);
        const float rx = px - fx, ry = py - fy, rz = pz - fz;
        const unsigned int ix = (unsigned int)(int)fx;
        const unsigned int iy = (unsigned int)(int)fy;
        const unsigned int iz = (unsigned int)(int)fz;
        const float2* tb = (const float2*)gtable + (size_t)l * TSZ;
        float g0 = 0.0f, g1 = 0.0f;
        #pragma unroll
        for (int c = 0; c < 8; ++c) {
            const unsigned int bi = (c >> 2) & 1u;
            const unsigned int bj = (c >> 1) & 1u;
            const unsigned int bk = c & 1u;
            const unsigned int h = ((ix + bi)
                                  ^ ((iy + bj) * 2654435761u)
                                  ^ ((iz + bk) * 805459861u)) & TMASK;
            const float2 f = __ldg(&tb[h]);
            const float w = (bi ? rx : 1.0f - rx)
                          * (bj ? ry : 1.0f - ry)
                          * (bk ? rz : 1.0f - rz);
            g0 = fmaf(w, f.x, g0);
            g1 = fmaf(w, f.y, g1);
        }
        sg[m][l][0] = g0;
        sg[m][l][1] = g1;
    }
    __syncthreads();

    // ---- layer 0: x = sin(5*(pos @ W0 + b0)) -> swizzled x^T in smem ----
    {
        float pxr[8], pyr[8], pzr[8];
        #pragma unroll
        for (int i = 0; i < 8; ++i) {
            pxr[i] = sp[m0 + i][0];
            pyr[i] = sp[m0 + i][1];
            pzr[i] = sp[m0 + i][2];
        }
        float w0A[3][4], w0B[3][4];
        #pragma unroll
        for (int k = 0; k < 3; ++k) {
            const float4 a = __ldg((const float4*)(gW0 + k * DD + ct * 4));
            const float4 b = __ldg((const float4*)(gW0 + k * DD + 128 + ct * 4));
            w0A[k][0] = a.x; w0A[k][1] = a.y; w0A[k][2] = a.z; w0A[k][3] = a.w;
            w0B[k][0] = b.x; w0B[k][1] = b.y; w0B[k][2] = b.z; w0B[k][3] = b.w;
        }
        const float4 b0a = __ldg((const float4*)(gb0 + ct * 4));
        const float4 b0b = __ldg((const float4*)(gb0 + 128 + ct * 4));
        const float bA[4] = {b0a.x, b0a.y, b0a.z, b0a.w};
        const float bB[4] = {b0b.x, b0b.y, b0b.z, b0b.w};
        #pragma unroll
        for (int j = 0; j < 4; ++j) {
            float vA[8], vB[8];
            #pragma unroll
            for (int i = 0; i < 8; ++i) {
                vA[i] = __sinf(W0S * fmaf(pxr[i], w0A[0][j],
                               fmaf(pyr[i], w0A[1][j], fmaf(pzr[i], w0A[2][j], bA[j]))));
                vB[i] = __sinf(W0S * fmaf(pxr[i], w0B[0][j],
                               fmaf(pyr[i], w0B[1][j], fmaf(pzr[i], w0B[2][j], bB[j]))));
            }
            const int dA = ct * 4 + j;
            const int wA0 = dA * 64 + ((mg0 ^ xkey) << 2);
            *(float4*)(sx + wA0)            = make_float4(vA[0], vA[1], vA[2], vA[3]);
            *(float4*)(sx + (wA0 ^ 4))      = make_float4(vA[4], vA[5], vA[6], vA[7]);
            const int wB0 = wA0 + 128 * 64;
            *(float4*)(sx + wB0)            = make_float4(vB[0], vB[1], vB[2], vB[3]);
            *(float4*)(sx + (wB0 ^ 4))      = make_float4(vB[4], vB[5], vB[6], vB[7]);
        }
    }
    // sxT visibility handled by the barrier inside gemm's first iteration

    unsigned long long acc[8][4];  // [m][pair]: pairs (A0,A1),(A2,A3),(B0,B1),(B2,B3)

    // GEMM: acc = x @ Wg  (x read from swizzled sx, Wg streamed via cp.async)
    auto gemm = [&](const float* __restrict__ Wg) {
        #pragma unroll
        for (int i = 0; i < 8; ++i)
            #pragma unroll
            for (int jp = 0; jp < 4; ++jp) acc[i][jp] = 0ULL;

        // prologue: chunk 0 -> buf 0
        {
            const uint32_t dst = sW_base + tid * 16;
            const char* src = (const char*)Wg + tid * 16;
            #pragma unroll
            for (int q = 0; q < 4; ++q) cp16(dst + q * 4096, src + q * 4096);
            cp_commit();
        }
        #pragma unroll 1
        for (int c = 0; c < NCH; ++c) {
            cp_wait0();
            __syncthreads();
            if (c + 1 < NCH) {
                const uint32_t dst = sW_base + ((c + 1) & 1) * (KB * DD * 4) + tid * 16;
                const char* src = (const char*)Wg + (size_t)(c + 1) * KB * DD * 4 + tid * 16;
                #pragma unroll
                for (int q = 0; q < 4; ++q) cp16(dst + q * 4096, src + q * 4096);
                cp_commit();
            }
            const float* swb = sW + (c & 1) * (KB * DD);
            const int k0 = c * KB;
            #pragma unroll
            for (int kk = 0; kk < KB; ++kk) {
                const int k = k0 + kk;
                const int gw = ((mg0 ^ ((k >> 2) & 15)) << 2);
                const float* xrow = sx + k * 64;
                const float4 xa = *(const float4*)(xrow + gw);
                const float4 xb = *(const float4*)(xrow + (gw ^ 4));
                const ulonglong2 wA = *(const ulonglong2*)(swb + kk * DD + (ct << 2));
                const ulonglong2 wB = *(const ulonglong2*)(swb + kk * DD + 128 + (ct << 2));
                const float xv[8] = {xa.x, xa.y, xa.z, xa.w, xb.x, xb.y, xb.z, xb.w};
                #pragma unroll
                for (int i = 0; i < 8; ++i) {
                    const unsigned long long ax = pk2(xv[i], xv[i]);
                    ffma2(acc[i][0], ax, wA.x);
                    ffma2(acc[i][1], ax, wA.y);
                    ffma2(acc[i][2], ax, wB.x);
                    ffma2(acc[i][3], ax, wB.y);
                }
            }
        }
    };

    #pragma unroll 1
    for (int layer = 0; layer < LG; ++layer) {
        // ---- z = x @ Ws[layer] ----
        gemm(gWs + (size_t)layer * DD * DD);

        // ---- epilogue 1: x = sin(5*(z+bs)) + sin(2*pi*sigma*(g @ A)) ----
        __syncthreads();   // all warps done reading sx before overwrite
        {
            const float4 a0A = __ldg((const float4*)(gA + ((size_t)layer * 2 + 0) * DD + ct * 4));
            const float4 a0B = __ldg((const float4*)(gA + ((size_t)layer * 2 + 0) * DD + 128 + ct * 4));
            const float4 a1A = __ldg((const float4*)(gA + ((size_t)layer * 2 + 1) * DD + ct * 4));
            const float4 a1B = __ldg((const float4*)(gA + ((size_t)layer * 2 + 1) * DD + 128 + ct * 4));
            const float4 bsA4 = __ldg((const float4*)(gbs + layer * DD + ct * 4));
            const float4 bsB4 = __ldg((const float4*)(gbs + layer * DD + 128 + ct * 4));
            const float A0A[4] = {a0A.x, a0A.y, a0A.z, a0A.w};
            const float A0B[4] = {a0B.x, a0B.y, a0B.z, a0B.w};
            const float A1A[4] = {a1A.x, a1A.y, a1A.z, a1A.w};
            const float A1B[4] = {a1B.x, a1B.y, a1B.z, a1B.w};
            const float bsA[4] = {bsA4.x, bsA4.y, bsA4.z, bsA4.w};
            const float bsB[4] = {bsB4.x, bsB4.y, bsB4.z, bsB4.w};
            float g0r[8], g1r[8];
            #pragma unroll
            for (int i = 0; i < 8; ++i) {
                g0r[i] = sg[m0 + i][layer][0];
                g1r[i] = sg[m0 + i][layer][1];
            }
            const float sig2pi = 6.283185307179586f * (5.0f * (float)(1 << layer));
            #pragma unroll
            for (int jp = 0; jp < 2; ++jp) {
                float vA0[8], vA1[8], vB0[8], vB1[8];
                #pragma unroll
                for (int i = 0; i < 8; ++i) {
                    float zA0, zA1, zB0, zB1;
                    upk2(acc[i][jp], zA0, zA1);
                    upk2(acc[i][2 + jp], zB0, zB1);
                    const float gA0 = sig2pi * fmaf(g0r[i], A0A[2*jp],   g1r[i] * A1A[2*jp]);
                    const float gA1 = sig2pi * fmaf(g0r[i], A0A[2*jp+1], g1r[i] * A1A[2*jp+1]);
                    const float gB0 = sig2pi * fmaf(g0r[i], A0B[2*jp],   g1r[i] * A1B[2*jp]);
                    const float gB1 = sig2pi * fmaf(g0r[i], A0B[2*jp+1], g1r[i] * A1B[2*jp+1]);
                    vA0[i] = __sinf(W0S * (zA0 + bsA[2*jp]))   + __sinf(gA0);
                    vA1[i] = __sinf(W0S * (zA1 + bsA[2*jp+1])) + __sinf(gA1);
                    vB0[i] = __sinf(W0S * (zB0 + bsB[2*jp]))   + __sinf(gB0);
                    vB1[i] = __sinf(W0S * (zB1 + bsB[2*jp+1])) + __sinf(gB1);
                }
                #pragma unroll
                for (int s = 0; s < 2; ++s) {
                    const float* vA = s ? vA1 : vA0;
                    const float* vB = s ? vB1 : vB0;
                    const int dA = ct * 4 + 2 * jp + s;
                    const int wA0 = dA * 64 + ((mg0 ^ xkey) << 2);
                    *(float4*)(sx + wA0)       = make_float4(vA[0], vA[1], vA[2], vA[3]);
                    *(float4*)(sx + (wA0 ^ 4)) = make_float4(vA[4], vA[5], vA[6], vA[7]);
                    const int wB0 = wA0 + 128 * 64;
                    *(float4*)(sx + wB0)       = make_float4(vB[0], vB[1], vB[2], vB[3]);
                    *(float4*)(sx + (wB0 ^ 4)) = make_float4(vB[4], vB[5], vB[6], vB[7]);
                }
            }
        }
        // write -> read ordering handled by barrier in next gemm iter 0

        // ---- z2 = x @ Wh[layer] ----
        gemm(gWh + (size_t)layer * DD * DD);

        // ---- epilogue 2: gout (+)= sin(10*(z2+bh)) ----
        {
            const float4 bhA4 = __ldg((const float4*)(gbh + layer * DD + ct * 4));
            const float4 bhB4 = __ldg((const float4*)(gbh + layer * DD + 128 + ct * 4));
            const float bhA[4] = {bhA4.x, bhA4.y, bhA4.z, bhA4.w};
            const float bhB[4] = {bhB4.x, bhB4.y, bhB4.z, bhB4.w};
            #pragma unroll
            for (int i = 0; i < 8; ++i) {
                float sA[4], sB[4];
                #pragma unroll
                for (int jp = 0; jp < 2; ++jp) {
                    float zA0, zA1, zB0, zB1;
                    upk2(acc[i][jp], zA0, zA1);
                    upk2(acc[i][2 + jp], zB0, zB1);
                    sA[2*jp]   = __sinf(W0H * (zA0 + bhA[2*jp]));
                    sA[2*jp+1] = __sinf(W0H * (zA1 + bhA[2*jp+1]));
                    sB[2*jp]   = __sinf(W0H * (zB0 + bhB[2*jp]));
                    sB[2*jp+1] = __sinf(W0H * (zB1 + bhB[2*jp+1]));
                }
                float* orowA = gout + (size_t)(base + m0 + i) * DD + ct * 4;
                float* orowB = orowA + 128;
                if (layer == 0) {
                    *(float4*)orowA = make_float4(sA[0], sA[1], sA[2], sA[3]);
                    *(float4*)orowB = make_float4(sB[0], sB[1], sB[2], sB[3]);
                } else {
                    float4 oA = *(const float4*)orowA;
                    float4 oB = *(const float4*)orowB;
                    oA.x += sA[0]; oA.y += sA[1]; oA.z += sA[2]; oA.w += sA[3];
                    oB.x += sB[0]; oB.y += sB[1]; oB.z += sB[2]; oB.w += sB[3];
                    *(float4*)orowA = oA;
                    *(float4*)orowB = oB;
                }
            }
        }
    }
}

extern "C" void kernel_launch(void* const* d_in, const int* in_sizes, int n_in,
                              void* d_out, int out_size) {
    const float* gpos   = (const float*)d_in[0];
    const float* gtable = (const float*)d_in[1];
    const float* gA     = (const float*)d_in[2];
    const float* gW0    = (const float*)d_in[3];
    const float* gb0    = (const float*)d_in[4];
    const float* gWs    = (const float*)d_in[5];
    const float* gbs    = (const float*)d_in[6];
    const float* gWh    = (const float*)d_in[7];
    const float* gbh    = (const float*)d_in[8];
    float* gout = (float*)d_out;

    const int n = in_sizes[0] / 3;
    cudaFuncSetAttribute(ffb_kernel, cudaFuncAttributeMaxDynamicSharedMemorySize, SMEM_BYTES);
    ffb_kernel<<<n / MPTS, NTHR, SMEM_BYTES>>>(gpos, gtable, gA, gW0, gb0,
                                               gWs, gbs, gWh, gbh, gout);
}

// round 8
// speedup vs baseline: 2.5666x; 2.0278x over previous
#include <cuda_runtime.h>
#include <cuda_bf16.h>
#include <cstdint>

#define LG 6
#define TSZ 524288
#define TMASK 0x7FFFFu
#define MPTS 64
#define NTHR 256
#define W0S 5.0f
#define W0H 10.0f

// smem byte map
#define SM_XHI 0            // bf16 x_hi [64][256], swizzled, 32KB
#define SM_XLO 32768        // bf16 x_lo, 32KB
#define SM_W   65536        // 2 x (32KB Whi + 32KB Wlo) phase buffers
#define SM_SG  196608       // float[64*12]
#define SM_SP  199680       // float[64*3]
#define SMEM_BYTES 200448

// [g][split][phase][n=256][128B swizzled row] ; g = layer*2 + (0=Ws,1=Wh)
__device__ __align__(128) unsigned char g_wscratch[12 * 2 * 4 * 32768];

// ---------------- helpers ----------------
static __device__ __forceinline__ uint32_t smem_u32(const void* p) {
    uint32_t a;
    asm("{ .reg .u64 t; cvta.to.shared.u64 t, %1; cvt.u32.u64 %0, t; }" : "=r"(a) : "l"(p));
    return a;
}
static __device__ __forceinline__ void cp16(uint32_t s, const void* g) {
    asm volatile("cp.async.cg.shared.global [%0], [%1], 16;" :: "r"(s), "l"(g));
}
static __device__ __forceinline__ void cp_commit() {
    asm volatile("cp.async.commit_group;" ::: "memory");
}
static __device__ __forceinline__ void cp_wait0() {
    asm volatile("cp.async.wait_group 0;" ::: "memory");
}
#define LDM4(r, addr) \
    asm volatile("ldmatrix.sync.aligned.m8n8.x4.shared.b16 {%0,%1,%2,%3}, [%4];" \
        : "=r"((r)[0]), "=r"((r)[1]), "=r"((r)[2]), "=r"((r)[3]) : "r"(addr))

static __device__ __forceinline__ void mma16816(float* d, const uint32_t* a,
                                                uint32_t b0, uint32_t b1) {
    asm volatile(
        "mma.sync.aligned.m16n8k16.row.col.f32.bf16.bf16.f32 "
        "{%0,%1,%2,%3}, {%4,%5,%6,%7}, {%8,%9}, {%0,%1,%2,%3};"
        : "+f"(d[0]), "+f"(d[1]), "+f"(d[2]), "+f"(d[3])
        : "r"(a[0]), "r"(a[1]), "r"(a[2]), "r"(a[3]), "r"(b0), "r"(b1));
}

// write one (row, d0..d0+1) pair into swizzled x_hi / x_lo tiles
static __device__ __forceinline__ void store_x(char* sb, int row, int d0, float va, float vb) {
    const int unit = (d0 >> 3) & 7;
    const int byte = row * 512 + ((d0 >> 6) << 7) + ((unit ^ (row & 7)) << 4) + (d0 & 7) * 2;
    const __nv_bfloat16 ha = __float2bfloat16(va), hb = __float2bfloat16(vb);
    const __nv_bfloat16 la = __float2bfloat16(va - __bfloat162float(ha));
    const __nv_bfloat16 lb = __float2bfloat16(vb - __bfloat162float(hb));
    *(uint32_t*)(sb + SM_XHI + byte) =
        (uint32_t)__bfloat16_as_ushort(ha) | ((uint32_t)__bfloat16_as_ushort(hb) << 16);
    *(uint32_t*)(sb + SM_XLO + byte) =
        (uint32_t)__bfloat16_as_ushort(la) | ((uint32_t)__bfloat16_as_ushort(lb) << 16);
}

// ---------------- prep: split W into bf16 hi/lo, ldmatrix-B layout ----------------
// layout: base + g*262144 + split*131072 + phase*32768 + n*128 + ((u ^ (n&7))<<4)
__global__ void prep_kernel(const float* __restrict__ gWs, const float* __restrict__ gWh) {
    const int idx = blockIdx.x * blockDim.x + threadIdx.x;  // 12*8192
    const int n  = idx & 255;
    const int ku = (idx >> 8) & 31;
    const int g  = idx >> 13;
    const float* src = ((g & 1) ? gWh : gWs) + (size_t)(g >> 1) * 65536;
    const int c = ku >> 3, u = ku & 7;
    unsigned short hi8[8], lo8[8];
    #pragma unroll
    for (int j = 0; j < 8; j++) {
        const int k = c * 64 + u * 8 + j;
        const float w = __ldg(&src[k * 256 + n]);
        const __nv_bfloat16 h = __float2bfloat16(w);
        const __nv_bfloat16 l = __float2bfloat16(w - __bfloat162float(h));
        hi8[j] = __bfloat16_as_ushort(h);
        lo8[j] = __bfloat16_as_ushort(l);
    }
    const size_t off = (size_t)c * 32768 + n * 128 + ((u ^ (n & 7)) << 4);
    unsigned char* bp = g_wscratch + (size_t)g * 262144;
    *(uint4*)(bp + off)          = *(uint4*)hi8;
    *(uint4*)(bp + 131072 + off) = *(uint4*)lo8;
}

// ---------------- main fused kernel ----------------
__global__ void __launch_bounds__(NTHR, 1)
ffb_kernel(const float* __restrict__ gpos,
           const float* __restrict__ gtable,
           const float* __restrict__ gA,
           const float* __restrict__ gW0,
           const float* __restrict__ gb0,
           const float* __restrict__ gbs,
           const float* __restrict__ gbh,
           float* __restrict__ gout)
{
    extern __shared__ float sf[];
    char* sb = (char*)sf;
    const uint32_t su = smem_u32(sf);
    const int tid = threadIdx.x, wid = tid >> 5, lane = tid & 31;
    const int base = blockIdx.x * MPTS;
    float* sg  = sf + SM_SG / 4;
    float* spp = sf + SM_SP / 4;

    for (int i = tid; i < MPTS * 3; i += NTHR) spp[i] = gpos[(size_t)base * 3 + i];
    __syncthreads();

    // ---- hash grid: 64 pts x 6 levels ----
    for (int t = tid; t < MPTS * LG; t += NTHR) {
        const int m = t / LG, l = t % LG;
        const float scale = (float)(16 << l);
        const float px = (spp[m * 3 + 0] + 1.0f) * 0.5f * scale;
        const float py = (spp[m * 3 + 1] + 1.0f) * 0.5f * scale;
        const float pz = (spp[m * 3 + 2] + 1.0f) * 0.5f * scale;
        const float fx = floorf(px), fy = floorf(py), fz = floorf(pz);
        const float rx = px - fx, ry = py - fy, rz = pz - fz;
        const unsigned ix = (unsigned)(int)fx, iy = (unsigned)(int)fy, iz = (unsigned)(int)fz;
        const float2* tbl = (const float2*)gtable + (size_t)l * TSZ;
        float g0 = 0.0f, g1 = 0.0f;
        #pragma unroll
        for (int c = 0; c < 8; ++c) {
            const unsigned bi = (c >> 2) & 1u, bj = (c >> 1) & 1u, bk = c & 1u;
            const unsigned h = ((ix + bi) ^ ((iy + bj) * 2654435761u)
                              ^ ((iz + bk) * 805459861u)) & TMASK;
            const float2 f = __ldg(&tbl[h]);
            const float w = (bi ? rx : 1.0f - rx) * (bj ? ry : 1.0f - ry) * (bk ? rz : 1.0f - rz);
            g0 = fmaf(w, f.x, g0);
            g1 = fmaf(w, f.y, g1);
        }
        sg[m * 12 + l * 2 + 0] = g0;
        sg[m * 12 + l * 2 + 1] = g1;
    }
    __syncthreads();

    // warp tiling: 4 m-strips (16 rows) x 2 n-halves (128 cols)
    const int ms = wid & 3, nh = wid >> 2;
    const int m0 = ms * 16, ncol0 = nh * 128;
    // lane constants
    const int rowA = m0 + (lane & 15);
    const int aku  = lane >> 4;                       // A k-subunit
    const int r1 = m0 + (lane >> 2), r2 = r1 + 8;     // D-frag rows
    const int dq = (lane & 3) * 2;                    // D-frag col pair
    const int nB = (lane & 7) + ((lane >> 4) << 3);   // B-frag n row base (local)
    const int uB = (lane >> 3) & 1;                   // B k-subunit

    // ---- layer 0: x = sin(5*(pos@W0+b0)) -> x tiles ----
    {
        const float px1 = spp[r1 * 3], py1 = spp[r1 * 3 + 1], pz1 = spp[r1 * 3 + 2];
        const float px2 = spp[r2 * 3], py2 = spp[r2 * 3 + 1], pz2 = spp[r2 * 3 + 2];
        #pragma unroll
        for (int nt = 0; nt < 16; nt++) {
            const int d0 = ncol0 + nt * 8 + dq;
            const float2 w0 = __ldg((const float2*)(gW0 + d0));
            const float2 w1 = __ldg((const float2*)(gW0 + 256 + d0));
            const float2 w2 = __ldg((const float2*)(gW0 + 512 + d0));
            const float2 bb = __ldg((const float2*)(gb0 + d0));
            const float v00 = __sinf(W0S * fmaf(px1, w0.x, fmaf(py1, w1.x, fmaf(pz1, w2.x, bb.x))));
            const float v01 = __sinf(W0S * fmaf(px1, w0.y, fmaf(py1, w1.y, fmaf(pz1, w2.y, bb.y))));
            const float v10 = __sinf(W0S * fmaf(px2, w0.x, fmaf(py2, w1.x, fmaf(pz2, w2.x, bb.x))));
            const float v11 = __sinf(W0S * fmaf(px2, w0.y, fmaf(py2, w1.y, fmaf(pz2, w2.y, bb.y))));
            store_x(sb, r1, d0, v00, v01);
            store_x(sb, r2, d0, v10, v11);
        }
    }

    float acc[16][4];
    float oacc[16][4];
    #pragma unroll
    for (int i = 0; i < 16; i++)
        #pragma unroll
        for (int q = 0; q < 4; q++) oacc[i][q] = 0.0f;

    // GEMM: acc = x @ W[g]  (3-term bf16 split, fp32 accum)
    auto do_gemm = [&](int g) {
        #pragma unroll
        for (int i = 0; i < 16; i++)
            #pragma unroll
            for (int q = 0; q < 4; q++) acc[i][q] = 0.0f;
        const unsigned char* wsrc = g_wscratch + (size_t)g * 262144;
        auto copy_phase = [&](int p, int buf) {
            const uint32_t dst = su + SM_W + buf * 65536 + tid * 16;
            const unsigned char* src = wsrc + (size_t)p * 32768 + tid * 16;
            #pragma unroll
            for (int q = 0; q < 8; q++) {
                cp16(dst + q * 4096, src + q * 4096);
                cp16(dst + 32768 + q * 4096, src + 131072 + q * 4096);
            }
            cp_commit();
        };
        copy_phase(0, 0);
        #pragma unroll 1
        for (int p = 0; p < 4; p++) {
            cp_wait0();
            __syncthreads();
            if (p < 3) copy_phase(p + 1, (p + 1) & 1);
            const uint32_t wb = su + SM_W + (p & 1) * 65536;
            #pragma unroll
            for (int ks = 0; ks < 4; ks++) {
                uint32_t ahi[4], alo[4];
                const uint32_t ax = (uint32_t)(rowA * 512 + p * 128
                                  + ((((ks << 1) + aku) ^ (rowA & 7)) << 4));
                LDM4(ahi, su + SM_XHI + ax);
                LDM4(alo, su + SM_XLO + ax);
                const uint32_t bsw = ((((ks << 1) + uB) ^ (lane & 7)) << 4);
                #pragma unroll
                for (int np = 0; np < 8; np++) {
                    uint32_t bh[4], bl[4];
                    const uint32_t bo = (uint32_t)((ncol0 + nB + np * 16) * 128) + bsw;
                    LDM4(bh, wb + bo);
                    LDM4(bl, wb + 32768 + bo);
                    mma16816(acc[np * 2],     ahi, bh[0], bh[1]);
                    mma16816(acc[np * 2 + 1], ahi, bh[2], bh[3]);
                    mma16816(acc[np * 2],     alo, bh[0], bh[1]);
                    mma16816(acc[np * 2 + 1], alo, bh[2], bh[3]);
                    mma16816(acc[np * 2],     ahi, bl[0], bl[1]);
                    mma16816(acc[np * 2 + 1], ahi, bl[2], bl[3]);
                }
            }
        }
        __syncthreads();
    };

    #pragma unroll 1
    for (int layer = 0; layer < LG; layer++) {
        // ===== z = x @ Ws =====
        do_gemm(layer * 2);
        // ---- epilogue 1: x = sin(5(z+bs)) + sin(sig*(g@A)) ----
        {
            const float g01 = sg[r1 * 12 + layer * 2], g11 = sg[r1 * 12 + layer * 2 + 1];
            const float g02 = sg[r2 * 12 + layer * 2], g12 = sg[r2 * 12 + layer * 2 + 1];
            const float s2 = 6.283185307179586f * (5.0f * (float)(1 << layer));
            #pragma unroll
            for (int nt = 0; nt < 16; nt++) {
                const int d0 = ncol0 + nt * 8 + dq;
                const float2 bs = __ldg((const float2*)(gbs + layer * 256 + d0));
                const float2 a0 = __ldg((const float2*)(gA + layer * 512 + d0));
                const float2 a1 = __ldg((const float2*)(gA + layer * 512 + 256 + d0));
                const float v00 = __sinf(W0S * (acc[nt][0] + bs.x))
                                + __sinf(s2 * fmaf(g01, a0.x, g11 * a1.x));
                const float v01 = __sinf(W0S * (acc[nt][1] + bs.y))
                                + __sinf(s2 * fmaf(g01, a0.y, g11 * a1.y));
                const float v10 = __sinf(W0S * (acc[nt][2] + bs.x))
                                + __sinf(s2 * fmaf(g02, a0.x, g12 * a1.x));
                const float v11 = __sinf(W0S * (acc[nt][3] + bs.y))
                                + __sinf(s2 * fmaf(g02, a0.y, g12 * a1.y));
                store_x(sb, r1, d0, v00, v01);
                store_x(sb, r2, d0, v10, v11);
            }
        }
        // ===== z2 = x @ Wh =====
        do_gemm(layer * 2 + 1);
        // ---- epilogue 2: out += sin(10(z2+bh)) (registers) ----
        {
            #pragma unroll
            for (int nt = 0; nt < 16; nt++) {
                const int d0 = ncol0 + nt * 8 + dq;
                const float2 bh = __ldg((const float2*)(gbh + layer * 256 + d0));
                oacc[nt][0] += __sinf(W0H * (acc[nt][0] + bh.x));
                oacc[nt][1] += __sinf(W0H * (acc[nt][1] + bh.y));
                oacc[nt][2] += __sinf(W0H * (acc[nt][2] + bh.x));
                oacc[nt][3] += __sinf(W0H * (acc[nt][3] + bh.y));
            }
        }
    }

    // ---- writeback ----
    #pragma unroll
    for (int nt = 0; nt < 16; nt++) {
        const int d0 = ncol0 + nt * 8 + dq;
        *(float2*)(gout + (size_t)(base + r1) * 256 + d0) = make_float2(oacc[nt][0], oacc[nt][1]);
        *(float2*)(gout + (size_t)(base + r2) * 256 + d0) = make_float2(oacc[nt][2], oacc[nt][3]);
    }
}

extern "C" void kernel_launch(void* const* d_in, const int* in_sizes, int n_in,
                              void* d_out, int out_size) {
    const float* gpos   = (const float*)d_in[0];
    const float* gtable = (const float*)d_in[1];
    const float* gA     = (const float*)d_in[2];
    const float* gW0    = (const float*)d_in[3];
    const float* gb0    = (const float*)d_in[4];
    const float* gWs    = (const float*)d_in[5];
    const float* gbs    = (const float*)d_in[6];
    const float* gWh    = (const float*)d_in[7];
    const float* gbh    = (const float*)d_in[8];
    float* gout = (float*)d_out;

    const int n = in_sizes[0] / 3;
    prep_kernel<<<384, 256>>>(gWs, gWh);
    cudaFuncSetAttribute(ffb_kernel, cudaFuncAttributeMaxDynamicSharedMemorySize, SMEM_BYTES);
    ffb_kernel<<<n / MPTS, NTHR, SMEM_BYTES>>>(gpos, gtable, gA, gW0, gb0, gbs, gbh, gout);
}